// round 7
// baseline (speedup 1.0000x reference)
#include <cuda_runtime.h>
#include <cstdint>
#include <cstddef>

// ---------------------------------------------------------------------------
// HGNN_conv via tf32 mma.sync:
//   yT  = (x @ W)^T            [128f, 16384n]   (rna-rounded on store)
//   eyT = raw MT @ y, as [f][e], split-K atomics
//   out = 0.5 * D_e ⊙ (MT^T @ (D_v ⊙ ey))
// R7: R4 loop skeleton with single barrier per stage; STS of the streamed
// tile placed BETWEEN the two compute halves (LDG latency hidden, registers
// released mid-iteration); D_v folded into G3's streamed STS (scale pass
// removed); G3's raw eyT fragments rna'd at load.
// ---------------------------------------------------------------------------

#define NN   16384
#define NE   8192
#define CIN  256
#define FOUT 128

__device__ float g_yT [FOUT * NN];   // 8 MB
__device__ float g_eyT[FOUT * NE];   // 4 MB (raw)
__device__ float g_wt [FOUT * CIN];  // 128 KB

#define BM 128
#define BN 128
#define BK 32
#define NTHR 256
#define SA0 36            // As stride (floats), CONF0 layout [m][k]
#define SA1 136           // As stride (floats), CONF1 layout [k][m]
#define SB  36            // Bs stride (floats), [n][k]
#define STAGE_FLOATS 9216 // 36864 B / 4
#define B_OFF_F 4608      // 18432 B / 4
#define SMEM_BYTES 73728  // 2 stages

// ---------------- helpers ----------------
static __device__ __forceinline__ uint32_t smem_u32(const void* p) {
    uint32_t a;
    asm("{ .reg .u64 t; cvta.to.shared.u64 t, %1; cvt.u32.u64 %0, t; }" : "=r"(a) : "l"(p));
    return a;
}
static __device__ __forceinline__ uint32_t rna(float x) {
    uint32_t o; asm("cvt.rna.tf32.f32 %0, %1;" : "=r"(o) : "f"(x)); return o;
}
static __device__ __forceinline__ float rnaf(float x) { return __uint_as_float(rna(x)); }
static __device__ __forceinline__ void cp16(uint32_t s, const void* g) {
    asm volatile("cp.async.cg.shared.global [%0], [%1], 16;" :: "r"(s), "l"(g) : "memory");
}
static __device__ __forceinline__ void cp_commit() {
    asm volatile("cp.async.commit_group;" ::: "memory");
}
template <int N>
static __device__ __forceinline__ void cp_wait() {
    asm volatile("cp.async.wait_group %0;" :: "n"(N) : "memory");
}
static __device__ __forceinline__ void sts4(uint32_t a, uint32_t x, uint32_t y,
                                            uint32_t z, uint32_t w) {
    asm volatile("st.shared.v4.b32 [%0], {%1, %2, %3, %4};"
                 :: "r"(a), "r"(x), "r"(y), "r"(z), "r"(w) : "memory");
}
static __device__ __forceinline__ void mma8(float& c0, float& c1, float& c2, float& c3,
                                            uint32_t a0, uint32_t a1, uint32_t a2, uint32_t a3,
                                            uint32_t b0, uint32_t b1) {
    asm volatile("mma.sync.aligned.m16n8k8.row.col.f32.tf32.tf32.f32 "
                 "{%0,%1,%2,%3}, {%4,%5,%6,%7}, {%8,%9}, {%0,%1,%2,%3};"
                 : "+f"(c0), "+f"(c1), "+f"(c2), "+f"(c3)
                 : "r"(a0), "r"(a1), "r"(a2), "r"(a3), "r"(b0), "r"(b1));
}

// ---------------- small kernels ----------------
__global__ void zero2_kernel(float* __restrict__ a, size_t na4,
                             float* __restrict__ b, size_t nb4) {
    size_t i = (size_t)blockIdx.x * blockDim.x + threadIdx.x;
    size_t st = (size_t)gridDim.x * blockDim.x;
    float4 z = make_float4(0.f, 0.f, 0.f, 0.f);
    for (size_t j = i; j < na4; j += st) reinterpret_cast<float4*>(a)[j] = z;
    for (size_t j = i; j < nb4; j += st) reinterpret_cast<float4*>(b)[j] = z;
}
__global__ void prep_wt_kernel(const float* __restrict__ W, float* __restrict__ wt) {
    int idx = blockIdx.x * blockDim.x + threadIdx.x;
    if (idx < FOUT * CIN) {
        int f = idx % FOUT, c = idx / FOUT;
        wt[f * CIN + c] = rnaf(W[c * FOUT + f]);
    }
}

// ---------------- main GEMM ----------------
// CONF 0: A resident pre-rounded [m][k] (cp.async); B streamed LDG->rna->STS [n][k]
// CONF 1: A streamed LDG->rna(kscale[k]*v)->STS, stored [k][m];
//         B resident RAW [n][k] (cp.async), rna at fragment load
// EPI  0: direct store with rna   1: atomicAdd   2: atomicAdd * 0.5*rowscale[m]
template <int CONF, int EPI>
__global__ __launch_bounds__(NTHR)
void mmak(const float* __restrict__ Ag, int lda,
          const float* __restrict__ Bg, int ldb,
          float* __restrict__ Cg, int ldc,
          const float* __restrict__ rowscale,
          const float* __restrict__ kscale,
          int k_chunk)
{
    extern __shared__ float sm[];
    const int t    = threadIdx.x;
    const int lane = t & 31, wid = t >> 5;
    const int g = lane >> 2, tg = lane & 3;
    const int wm = (wid & 1) * 64, wn = (wid >> 1) * 32;
    const int m0 = blockIdx.x * BM, n0 = blockIdx.y * BN;
    const int kbase = blockIdx.z * k_chunk;
    const int KT = k_chunk / BK;

    float acc[4][4][4];
    #pragma unroll
    for (int a = 0; a < 4; ++a)
        #pragma unroll
        for (int b = 0; b < 4; ++b)
            #pragma unroll
            for (int c = 0; c < 4; ++c) acc[a][b][c] = 0.f;

    float4 rg[4];
    float  rs = 1.0f;   // CONF1: per-row D_v scale paired with rg

    // ---- streamed LDG into regs for tile kt ----
    auto ldg_stream = [&](int kt) {
        const int kk = kbase + kt * BK;
        if (CONF == 0) {
            const int n = t >> 1, h = t & 1;
            const float4* src = reinterpret_cast<const float4*>(
                Bg + (size_t)(n0 + n) * ldb + kk + h * 16);
            #pragma unroll
            for (int j = 0; j < 4; ++j) rg[j] = src[j];
        } else {
            const int kr = t >> 3, ml = (t & 7) * 16;
            const float4* src = reinterpret_cast<const float4*>(
                Ag + (size_t)(kk + kr) * lda + m0 + ml);
            #pragma unroll
            for (int j = 0; j < 4; ++j) rg[j] = src[j];
            rs = kscale[kk + kr];
        }
    };
    // ---- STS streamed regs (with rna, and kscale for CONF1) into stage s ----
    auto sts_stream = [&](int s) {
        float* base = sm + s * STAGE_FLOATS;
        if (CONF == 0) {
            const int n = t >> 1, h = t & 1;
            uint32_t a = smem_u32(base + B_OFF_F + n * SB + h * 16);
            #pragma unroll
            for (int j = 0; j < 4; ++j)
                sts4(a + j * 16, rna(rg[j].x), rna(rg[j].y), rna(rg[j].z), rna(rg[j].w));
        } else {
            const int kr = t >> 3, ml = (t & 7) * 16;
            uint32_t a = smem_u32(base + kr * SA1 + ml);
            #pragma unroll
            for (int j = 0; j < 4; ++j)
                sts4(a + j * 16, rna(rs * rg[j].x), rna(rs * rg[j].y),
                                 rna(rs * rg[j].z), rna(rs * rg[j].w));
        }
    };
    // ---- resident operand via cp.async into stage s ----
    auto cp_res = [&](int s, int kt) {
        const int kk = kbase + kt * BK;
        float* base = sm + s * STAGE_FLOATS;
        const int r = t >> 1, h = t & 1;
        if (CONF == 0) {
            const float* src = Ag + (size_t)(m0 + r) * lda + kk + h * 16;
            uint32_t a = smem_u32(base + r * SA0 + h * 16);
            #pragma unroll
            for (int j = 0; j < 4; ++j) cp16(a + j * 16, src + j * 4);
        } else {
            const float* src = Bg + (size_t)(n0 + r) * ldb + kk + h * 16;
            uint32_t a = smem_u32(base + B_OFF_F + r * SB + h * 16);
            #pragma unroll
            for (int j = 0; j < 4; ++j) cp16(a + j * 16, src + j * 4);
        }
    };
    // ---- compute half-stage: ks = 2h, 2h+1 ----
    auto compute_half = [&](int s, int h) {
        const float* As = sm + s * STAGE_FLOATS;
        const float* Bs = As + B_OFF_F;
        #pragma unroll
        for (int ks = 2 * h; ks < 2 * h + 2; ++ks) {
            const int k8 = ks * 8;
            uint32_t af[4][4], bf[4][2];
            #pragma unroll
            for (int mi = 0; mi < 4; ++mi) {
                const int r0 = wm + mi * 16 + g, r1 = r0 + 8;
                const int c0 = k8 + tg, c1 = c0 + 4;
                if (CONF == 0) {   // pre-rounded A
                    af[mi][0] = __float_as_uint(As[r0 * SA0 + c0]);
                    af[mi][1] = __float_as_uint(As[r1 * SA0 + c0]);
                    af[mi][2] = __float_as_uint(As[r0 * SA0 + c1]);
                    af[mi][3] = __float_as_uint(As[r1 * SA0 + c1]);
                } else {           // rounded at STS
                    af[mi][0] = __float_as_uint(As[c0 * SA1 + r0]);
                    af[mi][1] = __float_as_uint(As[c0 * SA1 + r1]);
                    af[mi][2] = __float_as_uint(As[c1 * SA1 + r0]);
                    af[mi][3] = __float_as_uint(As[c1 * SA1 + r1]);
                }
            }
            #pragma unroll
            for (int ni = 0; ni < 4; ++ni) {
                const int nr = wn + ni * 8 + g;
                if (CONF == 0) {   // rounded at STS
                    bf[ni][0] = __float_as_uint(Bs[nr * SB + k8 + tg]);
                    bf[ni][1] = __float_as_uint(Bs[nr * SB + k8 + tg + 4]);
                } else {           // raw eyT: rna here
                    bf[ni][0] = rna(Bs[nr * SB + k8 + tg]);
                    bf[ni][1] = rna(Bs[nr * SB + k8 + tg + 4]);
                }
            }
            #pragma unroll
            for (int mi = 0; mi < 4; ++mi)
                #pragma unroll
                for (int ni = 0; ni < 4; ++ni)
                    mma8(acc[mi][ni][0], acc[mi][ni][1], acc[mi][ni][2], acc[mi][ni][3],
                         af[mi][0], af[mi][1], af[mi][2], af[mi][3],
                         bf[ni][0], bf[ni][1]);
        }
    };

    // ---- prologue: fill stage 0 ----
    ldg_stream(0);
    sts_stream(0);
    cp_res(0, 0);
    cp_commit();
    cp_wait<0>();
    __syncthreads();

    // ---- main loop: one barrier per stage, STS mid-compute ----
    for (int kt = 0; kt < KT; ++kt) {
        const int cur = kt & 1, nxt = cur ^ 1;
        const bool more = (kt + 1 < KT);
        if (more) {
            ldg_stream(kt + 1);          // DRAM latency spans cp_res + half compute
            cp_res(nxt, kt + 1);
            cp_commit();
        }
        compute_half(cur, 0);            // ks 0,1
        if (more) sts_stream(nxt);       // rg is ~300-400 cyc old here
        compute_half(cur, 1);            // ks 2,3
        if (more) cp_wait<0>();
        __syncthreads();
    }

    // ---- epilogue ----
    #pragma unroll
    for (int mi = 0; mi < 4; ++mi) {
        const int r0 = m0 + wm + mi * 16 + g;
        const int r1 = r0 + 8;
        #pragma unroll
        for (int ni = 0; ni < 4; ++ni) {
            const int c0 = n0 + wn + ni * 8 + tg * 2;
            float* p0 = Cg + (size_t)r0 * ldc + c0;
            float* p1 = Cg + (size_t)r1 * ldc + c0;
            if (EPI == 0) {
                p0[0] = rnaf(acc[mi][ni][0]); p0[1] = rnaf(acc[mi][ni][1]);
                p1[0] = rnaf(acc[mi][ni][2]); p1[1] = rnaf(acc[mi][ni][3]);
            } else if (EPI == 1) {
                atomicAdd(&p0[0], acc[mi][ni][0]); atomicAdd(&p0[1], acc[mi][ni][1]);
                atomicAdd(&p1[0], acc[mi][ni][2]); atomicAdd(&p1[1], acc[mi][ni][3]);
            } else {
                const float s0 = 0.5f * rowscale[r0];
                const float s1 = 0.5f * rowscale[r1];
                atomicAdd(&p0[0], s0 * acc[mi][ni][0]); atomicAdd(&p0[1], s0 * acc[mi][ni][1]);
                atomicAdd(&p1[0], s1 * acc[mi][ni][2]); atomicAdd(&p1[1], s1 * acc[mi][ni][3]);
            }
        }
    }
}

// ---------------- launch ----------------
extern "C" void kernel_launch(void* const* d_in, const int* in_sizes, int n_in,
                              void* d_out, int out_size) {
    const float *x = nullptr, *w = nullptr, *mt = nullptr, *dv = nullptr, *de = nullptr;
    for (int i = 0; i < n_in; ++i) {
        switch (in_sizes[i]) {
            case NN * CIN:   x  = (const float*)d_in[i]; break;
            case CIN * FOUT: w  = (const float*)d_in[i]; break;
            case 134217728:  mt = (const float*)d_in[i]; break;
            case NE:         dv = (const float*)d_in[i]; break;
            case NN:         de = (const float*)d_in[i]; break;
        }
    }
    float* out = (float*)d_out;
    float *yT, *eyT, *wt;
    { void* p; cudaGetSymbolAddress(&p, g_yT);  yT  = (float*)p; }
    { void* p; cudaGetSymbolAddress(&p, g_eyT); eyT = (float*)p; }
    { void* p; cudaGetSymbolAddress(&p, g_wt);  wt  = (float*)p; }

    cudaFuncSetAttribute(mmak<0, 0>, cudaFuncAttributeMaxDynamicSharedMemorySize, SMEM_BYTES);
    cudaFuncSetAttribute(mmak<0, 1>, cudaFuncAttributeMaxDynamicSharedMemorySize, SMEM_BYTES);
    cudaFuncSetAttribute(mmak<1, 2>, cudaFuncAttributeMaxDynamicSharedMemorySize, SMEM_BYTES);

    zero2_kernel<<<512, 256>>>(eyT, (size_t)(FOUT * NE) / 4, out, (size_t)(NN * FOUT) / 4);
    prep_wt_kernel<<<(FOUT * CIN + 255) / 256, 256>>>(w, wt);

    // G1: yT[f][n] = rna( sum_c wt[f][c] * x[n][c] )
    mmak<0, 0><<<dim3(1, NN / BN, 1), NTHR, SMEM_BYTES>>>(
        wt, CIN, x, CIN, yT, NN, nullptr, nullptr, CIN);

    // G2: eyT[f][e] += sum_n yT[f][n] * MT[e][n]   (split-K = 4, raw)
    mmak<0, 1><<<dim3(1, NE / BN, 4), NTHR, SMEM_BYTES>>>(
        yT, NN, mt, NN, eyT, NE, nullptr, nullptr, NN / 4);

    // G3: out[v][f] += 0.5*De[v] * sum_e (Dv[e]*MT[e][v]) * eyT[f][e]  (split-K = 2)
    mmak<1, 2><<<dim3(NN / BM, 1, 2), NTHR, SMEM_BYTES>>>(
        mt, NN, eyT, NE, out, FOUT, de, dv, NE / 2);
}

// round 8
// speedup vs baseline: 1.3685x; 1.3685x over previous
#include <cuda_runtime.h>
#include <cstdint>
#include <cstddef>

// ---------------------------------------------------------------------------
// HGNN_conv via tf32 mma.sync:
//   yT  = (x @ W)^T            [128f, 16384n]   (rna-rounded on store)
//   eyT = raw MT @ y, as [f][e], split-K atomics
//   eys = rna(D_v ⊙ ey)
//   out = 0.5 * D_e ⊙ (MT^T @ eys)
// R8: exact R4 structure (654us proven: loop schedule, scale pass, epilogues)
// with ONE change — fragment loads via ldmatrix.m8n8.x4.b16 (one 32-bit word
// per lane == tf32 fragment mapping): 24 scalar LDS -> 6 LDSM per warp-kstep
// on CONF0 (G1/G2) and on G3's resident B operand.
// ---------------------------------------------------------------------------

#define NN   16384
#define NE   8192
#define CIN  256
#define FOUT 128

__device__ float g_yT [FOUT * NN];   // 8 MB
__device__ float g_eyT[FOUT * NE];   // 4 MB
__device__ float g_wt [FOUT * CIN];  // 128 KB

#define BM 128
#define BN 128
#define BK 32
#define NTHR 256
#define SA0 36            // As stride (floats), CONF0 layout [m][k]; 144B = 16B-aligned
#define SA1 136           // As stride (floats), CONF1 layout [k][m]
#define SB  36            // Bs stride (floats), [n][k]
#define STAGE_FLOATS 9216 // 36864 B / 4
#define B_OFF_F 4608      // 18432 B / 4
#define SMEM_BYTES 73728  // 2 stages

// ---------------- helpers ----------------
static __device__ __forceinline__ uint32_t smem_u32(const void* p) {
    uint32_t a;
    asm("{ .reg .u64 t; cvta.to.shared.u64 t, %1; cvt.u32.u64 %0, t; }" : "=r"(a) : "l"(p));
    return a;
}
static __device__ __forceinline__ uint32_t rna(float x) {
    uint32_t o; asm("cvt.rna.tf32.f32 %0, %1;" : "=r"(o) : "f"(x)); return o;
}
static __device__ __forceinline__ float rnaf(float x) { return __uint_as_float(rna(x)); }
static __device__ __forceinline__ void cp16(uint32_t s, const void* g) {
    asm volatile("cp.async.cg.shared.global [%0], [%1], 16;" :: "r"(s), "l"(g) : "memory");
}
static __device__ __forceinline__ void cp_commit() {
    asm volatile("cp.async.commit_group;" ::: "memory");
}
static __device__ __forceinline__ void cp_wait0() {
    asm volatile("cp.async.wait_group 0;" ::: "memory");
}
static __device__ __forceinline__ void sts4(uint32_t a, uint32_t x, uint32_t y,
                                            uint32_t z, uint32_t w) {
    asm volatile("st.shared.v4.b32 [%0], {%1, %2, %3, %4};"
                 :: "r"(a), "r"(x), "r"(y), "r"(z), "r"(w) : "memory");
}
static __device__ __forceinline__ void ldsm4(uint32_t& r0, uint32_t& r1,
                                             uint32_t& r2, uint32_t& r3, uint32_t a) {
    asm volatile("ldmatrix.sync.aligned.m8n8.x4.shared.b16 {%0,%1,%2,%3}, [%4];"
                 : "=r"(r0), "=r"(r1), "=r"(r2), "=r"(r3) : "r"(a));
}
static __device__ __forceinline__ void mma8(float& c0, float& c1, float& c2, float& c3,
                                            uint32_t a0, uint32_t a1, uint32_t a2, uint32_t a3,
                                            uint32_t b0, uint32_t b1) {
    asm volatile("mma.sync.aligned.m16n8k8.row.col.f32.tf32.tf32.f32 "
                 "{%0,%1,%2,%3}, {%4,%5,%6,%7}, {%8,%9}, {%0,%1,%2,%3};"
                 : "+f"(c0), "+f"(c1), "+f"(c2), "+f"(c3)
                 : "r"(a0), "r"(a1), "r"(a2), "r"(a3), "r"(b0), "r"(b1));
}

// ---------------- small kernels ----------------
__global__ void zero2_kernel(float* __restrict__ a, size_t na4,
                             float* __restrict__ b, size_t nb4) {
    size_t i = (size_t)blockIdx.x * blockDim.x + threadIdx.x;
    size_t st = (size_t)gridDim.x * blockDim.x;
    float4 z = make_float4(0.f, 0.f, 0.f, 0.f);
    for (size_t j = i; j < na4; j += st) reinterpret_cast<float4*>(a)[j] = z;
    for (size_t j = i; j < nb4; j += st) reinterpret_cast<float4*>(b)[j] = z;
}
__global__ void prep_wt_kernel(const float* __restrict__ W, float* __restrict__ wt) {
    int idx = blockIdx.x * blockDim.x + threadIdx.x;
    if (idx < FOUT * CIN) {
        int f = idx % FOUT, c = idx / FOUT;
        wt[f * CIN + c] = rnaf(W[c * FOUT + f]);
    }
}
__global__ void scale_ey_kernel(float* __restrict__ eyT, const float* __restrict__ dv) {
    int i4 = blockIdx.x * blockDim.x + threadIdx.x;
    if (i4 < (FOUT * NE) / 4) {
        int e4 = (i4 * 4) & (NE - 1);
        float4 v = reinterpret_cast<float4*>(eyT)[i4];
        const float4 s = *reinterpret_cast<const float4*>(&dv[e4]);
        v.x = rnaf(v.x * s.x); v.y = rnaf(v.y * s.y);
        v.z = rnaf(v.z * s.z); v.w = rnaf(v.w * s.w);
        reinterpret_cast<float4*>(eyT)[i4] = v;
    }
}

// ---------------- main GEMM ----------------
// CONF 0: A resident (cp.async, pre-rounded) [m][k]; B streamed (LDG+rna+STS) [n][k]
// CONF 1: A streamed (LDG+rna+STS), source rows are k, stored [k][m]; B resident [n][k]
// EPI  0: direct store with rna   1: atomicAdd   2: atomicAdd * 0.5*rowscale[m]
template <int CONF, int EPI>
__global__ __launch_bounds__(NTHR)
void mmak(const float* __restrict__ Ag, int lda,
          const float* __restrict__ Bg, int ldb,
          float* __restrict__ Cg, int ldc,
          const float* __restrict__ rowscale,
          int k_chunk)
{
    extern __shared__ float sm[];
    const int t    = threadIdx.x;
    const int lane = t & 31, wid = t >> 5;
    const int g = lane >> 2, tg = lane & 3;
    const int wm = (wid & 1) * 64, wn = (wid >> 1) * 32;
    const int m0 = blockIdx.x * BM, n0 = blockIdx.y * BN;
    const int kbase = blockIdx.z * k_chunk;
    const int KT = k_chunk / BK;

    float acc[4][4][4];
    #pragma unroll
    for (int a = 0; a < 4; ++a)
        #pragma unroll
        for (int b = 0; b < 4; ++b)
            #pragma unroll
            for (int c = 0; c < 4; ++c) acc[a][b][c] = 0.f;

    float4 rg[4];

    // ldmatrix per-lane address offsets (floats) within a stage
    //   A (CONF0): row = wm + (lane&15), col-word = (lane>>4)*4
    //   B        : row = wn + (lane&7) + (lane>>4)*8, col-word = ((lane>>3)&1)*4
    const uint32_t aOffF = (uint32_t)((wm + (lane & 15)) * SA0 + (lane >> 4) * 4);
    const uint32_t bOffF = (uint32_t)((wn + (lane & 7) + (lane >> 4) * 8) * SB
                                      + ((lane >> 3) & 1) * 4);

    // ---- streamed LDG into regs for tile kt ----
    auto ldg_stream = [&](int kt) {
        const int kk = kbase + kt * BK;
        if (CONF == 0) {
            const int n = t >> 1, h = t & 1;
            const float4* src = reinterpret_cast<const float4*>(
                Bg + (size_t)(n0 + n) * ldb + kk + h * 16);
            #pragma unroll
            for (int j = 0; j < 4; ++j) rg[j] = src[j];
        } else {
            const int kr = t >> 3, ml = (t & 7) * 16;
            const float4* src = reinterpret_cast<const float4*>(
                Ag + (size_t)(kk + kr) * lda + m0 + ml);
            #pragma unroll
            for (int j = 0; j < 4; ++j) rg[j] = src[j];
        }
    };
    // ---- STS streamed regs (with rna) into stage s ----
    auto sts_stream = [&](int s) {
        float* base = sm + s * STAGE_FLOATS;
        uint32_t a;
        if (CONF == 0) {
            const int n = t >> 1, h = t & 1;
            a = smem_u32(base + B_OFF_F + n * SB + h * 16);
        } else {
            const int kr = t >> 3, ml = (t & 7) * 16;
            a = smem_u32(base + kr * SA1 + ml);
        }
        #pragma unroll
        for (int j = 0; j < 4; ++j)
            sts4(a + j * 16, rna(rg[j].x), rna(rg[j].y), rna(rg[j].z), rna(rg[j].w));
    };
    // ---- resident operand via cp.async into stage s ----
    auto cp_res = [&](int s, int kt) {
        const int kk = kbase + kt * BK;
        float* base = sm + s * STAGE_FLOATS;
        const int r = t >> 1, h = t & 1;
        if (CONF == 0) {
            const float* src = Ag + (size_t)(m0 + r) * lda + kk + h * 16;
            uint32_t a = smem_u32(base + r * SA0 + h * 16);
            #pragma unroll
            for (int j = 0; j < 4; ++j) cp16(a + j * 16, src + j * 4);
        } else {
            const float* src = Bg + (size_t)(n0 + r) * ldb + kk + h * 16;
            uint32_t a = smem_u32(base + B_OFF_F + r * SB + h * 16);
            #pragma unroll
            for (int j = 0; j < 4; ++j) cp16(a + j * 16, src + j * 4);
        }
    };
    // ---- compute one stage (LDSM fragment loads) ----
    auto compute = [&](int s) {
        const float* As = sm + s * STAGE_FLOATS;
        const float* Bs = As + B_OFF_F;
        const uint32_t aBase = smem_u32(As) + (aOffF << 2);
        const uint32_t bBase = smem_u32(Bs) + (bOffF << 2);
        #pragma unroll
        for (int ks = 0; ks < 4; ++ks) {
            const int k8 = ks * 8;
            uint32_t af[4][4], bf[4][2];
            if (CONF == 0) {
                #pragma unroll
                for (int mi = 0; mi < 4; ++mi)
                    ldsm4(af[mi][0], af[mi][1], af[mi][2], af[mi][3],
                          aBase + ks * 32 + mi * (16 * SA0 * 4));
            } else {
                #pragma unroll
                for (int mi = 0; mi < 4; ++mi) {
                    const int r0 = wm + mi * 16 + g, r1 = r0 + 8;
                    const int c0 = k8 + tg, c1 = c0 + 4;
                    af[mi][0] = __float_as_uint(As[c0 * SA1 + r0]);
                    af[mi][1] = __float_as_uint(As[c0 * SA1 + r1]);
                    af[mi][2] = __float_as_uint(As[c1 * SA1 + r0]);
                    af[mi][3] = __float_as_uint(As[c1 * SA1 + r1]);
                }
            }
            #pragma unroll
            for (int p = 0; p < 2; ++p)
                ldsm4(bf[2 * p][0], bf[2 * p][1], bf[2 * p + 1][0], bf[2 * p + 1][1],
                      bBase + ks * 32 + p * (16 * SB * 4));
            #pragma unroll
            for (int mi = 0; mi < 4; ++mi)
                #pragma unroll
                for (int ni = 0; ni < 4; ++ni)
                    mma8(acc[mi][ni][0], acc[mi][ni][1], acc[mi][ni][2], acc[mi][ni][3],
                         af[mi][0], af[mi][1], af[mi][2], af[mi][3],
                         bf[ni][0], bf[ni][1]);
        }
    };

    // ---- pipelined main loop (R4 schedule, unchanged) ----
    ldg_stream(0);
    sts_stream(0);
    cp_res(0, 0);
    cp_commit();
    for (int kt = 0; kt < KT; ++kt) {
        const int cur = kt & 1, nxt = cur ^ 1;
        if (kt + 1 < KT) ldg_stream(kt + 1);
        cp_wait0();
        __syncthreads();
        if (kt + 1 < KT) {
            sts_stream(nxt);
            cp_res(nxt, kt + 1);
            cp_commit();
        }
        compute(cur);
        __syncthreads();
    }

    // ---- epilogue ----
    #pragma unroll
    for (int mi = 0; mi < 4; ++mi) {
        const int r0 = m0 + wm + mi * 16 + g;
        const int r1 = r0 + 8;
        #pragma unroll
        for (int ni = 0; ni < 4; ++ni) {
            const int c0 = n0 + wn + ni * 8 + tg * 2;
            float* p0 = Cg + (size_t)r0 * ldc + c0;
            float* p1 = Cg + (size_t)r1 * ldc + c0;
            if (EPI == 0) {
                p0[0] = rnaf(acc[mi][ni][0]); p0[1] = rnaf(acc[mi][ni][1]);
                p1[0] = rnaf(acc[mi][ni][2]); p1[1] = rnaf(acc[mi][ni][3]);
            } else if (EPI == 1) {
                atomicAdd(&p0[0], acc[mi][ni][0]); atomicAdd(&p0[1], acc[mi][ni][1]);
                atomicAdd(&p1[0], acc[mi][ni][2]); atomicAdd(&p1[1], acc[mi][ni][3]);
            } else {
                const float s0 = 0.5f * rowscale[r0];
                const float s1 = 0.5f * rowscale[r1];
                atomicAdd(&p0[0], s0 * acc[mi][ni][0]); atomicAdd(&p0[1], s0 * acc[mi][ni][1]);
                atomicAdd(&p1[0], s1 * acc[mi][ni][2]); atomicAdd(&p1[1], s1 * acc[mi][ni][3]);
            }
        }
    }
}

// ---------------- launch ----------------
extern "C" void kernel_launch(void* const* d_in, const int* in_sizes, int n_in,
                              void* d_out, int out_size) {
    const float *x = nullptr, *w = nullptr, *mt = nullptr, *dv = nullptr, *de = nullptr;
    for (int i = 0; i < n_in; ++i) {
        switch (in_sizes[i]) {
            case NN * CIN:   x  = (const float*)d_in[i]; break;
            case CIN * FOUT: w  = (const float*)d_in[i]; break;
            case 134217728:  mt = (const float*)d_in[i]; break;
            case NE:         dv = (const float*)d_in[i]; break;
            case NN:         de = (const float*)d_in[i]; break;
        }
    }
    float* out = (float*)d_out;
    float *yT, *eyT, *wt;
    { void* p; cudaGetSymbolAddress(&p, g_yT);  yT  = (float*)p; }
    { void* p; cudaGetSymbolAddress(&p, g_eyT); eyT = (float*)p; }
    { void* p; cudaGetSymbolAddress(&p, g_wt);  wt  = (float*)p; }

    cudaFuncSetAttribute(mmak<0, 0>, cudaFuncAttributeMaxDynamicSharedMemorySize, SMEM_BYTES);
    cudaFuncSetAttribute(mmak<0, 1>, cudaFuncAttributeMaxDynamicSharedMemorySize, SMEM_BYTES);
    cudaFuncSetAttribute(mmak<1, 2>, cudaFuncAttributeMaxDynamicSharedMemorySize, SMEM_BYTES);

    zero2_kernel<<<512, 256>>>(eyT, (size_t)(FOUT * NE) / 4, out, (size_t)(NN * FOUT) / 4);
    prep_wt_kernel<<<(FOUT * CIN + 255) / 256, 256>>>(w, wt);

    // G1: yT[f][n] = rna( sum_c wt[f][c] * x[n][c] )
    mmak<0, 0><<<dim3(1, NN / BN, 1), NTHR, SMEM_BYTES>>>(
        wt, CIN, x, CIN, yT, NN, nullptr, CIN);

    // G2: eyT[f][e] += sum_n yT[f][n] * MT[e][n]   (split-K = 4)
    mmak<0, 1><<<dim3(1, NE / BN, 4), NTHR, SMEM_BYTES>>>(
        yT, NN, mt, NN, eyT, NE, nullptr, NN / 4);

    scale_ey_kernel<<<(FOUT * NE / 4 + 255) / 256, 256>>>(eyT, dv);

    // G3: out[v][f] += 0.5*De[v] * sum_e MT[e][v] * eyT[f][e]   (split-K = 2)
    mmak<1, 2><<<dim3(NN / BM, 1, 2), NTHR, SMEM_BYTES>>>(
        mt, NN, eyT, NE, out, FOUT, de, NE / 2);
}